// round 2
// baseline (speedup 1.0000x reference)
#include <cuda_runtime.h>
#include <stdint.h>

// EarthMoversDistanceRegularizer: segmented sort (200 contiguous segments of
// ~42K floats) + fused |x_sorted - initial_sorted| segment-mean reduction.
//
// Pipeline:
//   k_offsets : segment start offsets via binary search (201 threads)
//   k_hist    : float->sortable-uint convert + per-segment histograms of all
//               4 radix digits (one CTA / segment, warp-aggregated smem atomics)
//   k_pass<false> x3 : stable 8-bit LSD scatter passes (one CTA / segment)
//   k_pass<true>     : last pass fused with |diff| + per-segment mean
//   k_final   : mean over 200 segments * 1e-3 -> scalar

#define NSEG     200
#define NMAX     8388608
#define NTHREADS 1024
#define NWARPS   32
#define FULLMASK 0xffffffffu

__device__ uint32_t g_keyA[NMAX];
__device__ uint32_t g_keyB[NMAX];
__device__ int      g_off[NSEG + 1];
__device__ uint32_t g_hist[NSEG][4][256];
__device__ float    g_emd[NSEG];

__device__ __forceinline__ uint32_t flipf(uint32_t u) {
    return (u & 0x80000000u) ? ~u : (u | 0x80000000u);
}
__device__ __forceinline__ float unflip(uint32_t k) {
    uint32_t u = (k & 0x80000000u) ? (k & 0x7fffffffu) : ~k;
    return __uint_as_float(u);
}

// ---------------------------------------------------------------------------
__global__ void k_offsets(const int* __restrict__ seg, int n) {
    int s = threadIdx.x;
    if (s > NSEG) return;
    int lo = 0, hi = n;
    while (lo < hi) {
        int mid = (lo + hi) >> 1;
        if (seg[mid] < s) lo = mid + 1; else hi = mid;
    }
    g_off[s] = lo;
}

// ---------------------------------------------------------------------------
__global__ __launch_bounds__(NTHREADS) void k_hist(const float* __restrict__ x) {
    __shared__ uint32_t hist[4][256];
    const int s   = blockIdx.x;
    const int beg = g_off[s], end = g_off[s + 1];
    const int tid = threadIdx.x, lane = tid & 31;

    for (int i = tid; i < 4 * 256; i += NTHREADS) ((uint32_t*)hist)[i] = 0;
    __syncthreads();

    const int iters = (end - beg + NTHREADS - 1) / NTHREADS;
    const uint32_t lmask = (1u << lane) - 1u;
    for (int c = 0; c < iters; c++) {
        int i = beg + c * NTHREADS + tid;
        bool valid = i < end;
        uint32_t k = 0;
        if (valid) {
            k = flipf(__float_as_uint(x[i]));
            g_keyA[i] = k;
        }
        uint32_t vm = __ballot_sync(FULLMASK, valid);
#pragma unroll
        for (int p = 0; p < 4; p++) {
            uint32_t d = (k >> (8 * p)) & 255u;
            uint32_t m = __match_any_sync(FULLMASK, d) & vm;
            if (valid && ((m & lmask) == 0))   // leader of this digit group
                atomicAdd(&hist[p][d], (uint32_t)__popc(m));
        }
    }
    __syncthreads();
    for (int i = tid; i < 4 * 256; i += NTHREADS)
        ((uint32_t*)g_hist[s])[i] = ((uint32_t*)hist)[i];
}

// ---------------------------------------------------------------------------
// One CTA per segment. Stable rank: intra-warp via match_any, cross-warp via a
// per-chunk [digit][warp] count table (33-padded to avoid bank conflicts),
// cross-chunk via running per-digit base counters seeded from the precomputed
// digit histogram prefix.
template <bool FUSE>
__global__ __launch_bounds__(NTHREADS) void k_pass(int pass,
                                                   const float* __restrict__ init_sorted) {
    __shared__ uint32_t s_base[256];
    __shared__ uint32_t s_scan[256];
    __shared__ uint32_t s_tot[256];
    __shared__ uint32_t s_wdc[256 * 33];
    __shared__ float    s_red[NWARPS];

    const uint32_t* __restrict__ in  = (pass & 1) ? g_keyB : g_keyA;
    uint32_t*       __restrict__ out = (pass & 1) ? g_keyA : g_keyB;
    const int shift = 8 * pass;

    const int s   = blockIdx.x;
    const int beg = g_off[s], end = g_off[s + 1];
    const int tid = threadIdx.x, lane = tid & 31, warp = tid >> 5;
    const uint32_t lmask = (1u << lane) - 1u;

    // exclusive prefix of this pass's digit histogram -> scatter bases
    uint32_t own = 0;
    if (tid < 256) { own = g_hist[s][pass][tid]; s_scan[tid] = own; }
    __syncthreads();
    for (int o = 1; o < 256; o <<= 1) {
        uint32_t t = (tid < 256 && tid >= o) ? s_scan[tid - o] : 0;
        __syncthreads();
        if (tid < 256) s_scan[tid] += t;
        __syncthreads();
    }
    if (tid < 256) s_base[tid] = (uint32_t)beg + s_scan[tid] - own;
    __syncthreads();

    const int iters = (end - beg + NTHREADS - 1) / NTHREADS;
    float acc = 0.f;

    for (int c = 0; c < iters; c++) {
        int i = beg + c * NTHREADS + tid;
        bool valid = i < end;
        uint32_t k = valid ? in[i] : 0u;
        uint32_t d = (k >> shift) & 255u;

        uint32_t vm = __ballot_sync(FULLMASK, valid);
        uint32_t m  = __match_any_sync(FULLMASK, d) & vm;
        uint32_t lt = m & lmask;
        int  lrank  = __popc(lt);
        bool leader = valid && (lt == 0);
        int  cnt    = __popc(m);

        // zero the [digit][warp] table; each thread owns 8 padded slots
        // (previous chunk's reads are fenced by the barrier at loop bottom)
        {
            int row = tid >> 2;            // 0..255 (digit)
            int col = (tid & 3) << 3;      // 0,8,16,24
            uint32_t* z = &s_wdc[row * 33 + col];
#pragma unroll
            for (int j = 0; j < 8; j++) z[j] = 0;
        }
        __syncthreads();
        if (leader) s_wdc[d * 33 + warp] = (uint32_t)cnt;
        __syncthreads();
        if (tid < 256) {
            uint32_t run = 0;
#pragma unroll
            for (int w = 0; w < NWARPS; w++) {
                uint32_t t = s_wdc[tid * 33 + w];
                s_wdc[tid * 33 + w] = run;
                run += t;
            }
            s_tot[tid] = run;
        }
        __syncthreads();
        if (valid) {
            uint32_t pos = s_base[d] + s_wdc[d * 33 + warp] + (uint32_t)lrank;
            if (FUSE) {
                acc += fabsf(unflip(k) - init_sorted[pos]);
            } else {
                out[pos] = k;
            }
        }
        __syncthreads();
        if (tid < 256) s_base[tid] += s_tot[tid];
        __syncthreads();
    }

    if (FUSE) {
#pragma unroll
        for (int o = 16; o; o >>= 1) acc += __shfl_down_sync(FULLMASK, acc, o);
        if (lane == 0) s_red[warp] = acc;
        __syncthreads();
        if (warp == 0) {
            float v = (lane < NWARPS) ? s_red[lane] : 0.f;
#pragma unroll
            for (int o = 16; o; o >>= 1) v += __shfl_down_sync(FULLMASK, v, o);
            if (lane == 0) {
                int L = end - beg;
                g_emd[s] = (L > 0) ? v / (float)L : 0.f;
            }
        }
    }
}

// ---------------------------------------------------------------------------
__global__ void k_final(float* __restrict__ outp) {
    __shared__ float sh[256];
    int tid = threadIdx.x;
    sh[tid] = (tid < NSEG) ? g_emd[tid] : 0.f;
    __syncthreads();
    for (int o = 128; o; o >>= 1) {
        if (tid < o) sh[tid] += sh[tid + o];
        __syncthreads();
    }
    if (tid == 0) outp[0] = sh[0] * (1e-3f / (float)NSEG);
}

// ---------------------------------------------------------------------------
extern "C" void kernel_launch(void* const* d_in, const int* in_sizes, int n_in,
                              void* d_out, int out_size) {
    const float* x    = (const float*)d_in[0];
    const float* init = (const float*)d_in[1];
    const int*   seg  = (const int*)d_in[2];
    int n = in_sizes[0];

    k_offsets<<<1, 256>>>(seg, n);
    k_hist<<<NSEG, NTHREADS>>>(x);
    k_pass<false><<<NSEG, NTHREADS>>>(0, nullptr);
    k_pass<false><<<NSEG, NTHREADS>>>(1, nullptr);
    k_pass<false><<<NSEG, NTHREADS>>>(2, nullptr);
    k_pass<true ><<<NSEG, NTHREADS>>>(3, init);
    k_final<<<1, 256>>>((float*)d_out);
}

// round 3
// speedup vs baseline: 1.0682x; 1.0682x over previous
#include <cuda_runtime.h>
#include <stdint.h>

// EarthMoversDistanceRegularizer: segmented sort (200 contiguous segments of
// ~42K floats) + fused |x_sorted - initial_sorted| segment-mean reduction.
//
// v3: 16 items/thread (8192-elem chunks), uint16 cross-warp rank table,
//     smem exchange for coalesced scatter, fused last pass.

#define NSEG     200
#define NMAX     8388608
#define NT       512
#define NWARP    16
#define IT       16
#define CHUNK    (NT * IT)          // 8192
#define FULLMASK 0xffffffffu

__device__ uint32_t g_keyA[NMAX];
__device__ uint32_t g_keyB[NMAX];
__device__ int      g_off[NSEG + 1];
__device__ uint32_t g_hist[NSEG][4][256];
__device__ float    g_emd[NSEG];

__device__ __forceinline__ uint32_t flipf(uint32_t u) {
    return (u & 0x80000000u) ? ~u : (u | 0x80000000u);
}
__device__ __forceinline__ float unflip(uint32_t k) {
    uint32_t u = (k & 0x80000000u) ? (k & 0x7fffffffu) : ~k;
    return __uint_as_float(u);
}

// ---------------------------------------------------------------------------
__global__ void k_offsets(const int* __restrict__ seg, int n) {
    int s = threadIdx.x;
    if (s > NSEG) return;
    int lo = 0, hi = n;
    while (lo < hi) {
        int mid = (lo + hi) >> 1;
        if (seg[mid] < s) lo = mid + 1; else hi = mid;
    }
    g_off[s] = lo;
}

// ---------------------------------------------------------------------------
// Convert float -> sortable uint, store to g_keyA, and build per-segment
// histograms of all 4 radix digit positions (warp-aggregated smem atomics;
// high digits are heavily skewed for normal data, so aggregation matters).
__global__ __launch_bounds__(NT) void k_hist(const float* __restrict__ x) {
    __shared__ uint32_t hist[4][256];
    const int s   = blockIdx.x;
    const int beg = g_off[s], end = g_off[s + 1];
    const int tid = threadIdx.x, lane = tid & 31;
    const uint32_t lmask = (1u << lane) - 1u;

    for (int i = tid; i < 4 * 256; i += NT) ((uint32_t*)hist)[i] = 0;
    __syncthreads();

    const int iters = (end - beg + NT - 1) / NT;
    for (int c = 0; c < iters; c++) {
        int i = beg + c * NT + tid;
        bool valid = i < end;
        uint32_t k = 0;
        if (valid) {
            k = flipf(__float_as_uint(x[i]));
            g_keyA[i] = k;
        }
        uint32_t vm = __ballot_sync(FULLMASK, valid);
#pragma unroll
        for (int p = 0; p < 4; p++) {
            uint32_t d = (k >> (8 * p)) & 255u;
            uint32_t m = __match_any_sync(FULLMASK, d) & vm;
            if (valid && ((m & lmask) == 0))
                atomicAdd(&hist[p][d], (uint32_t)__popc(m));
        }
    }
    __syncthreads();
    for (int i = tid; i < 4 * 256; i += NT)
        ((uint32_t*)g_hist[s])[i] = ((uint32_t*)hist)[i];
}

// ---------------------------------------------------------------------------
// Exclusive prefix over 256 values held by threads 0..255 (others pass 0).
// All NT threads must call (contains barriers). Returns exclusive prefix.
__device__ __forceinline__ uint32_t scan256(uint32_t v, int tid,
                                            uint32_t* s_wsum) {
    int lane = tid & 31, w = tid >> 5;
    uint32_t inc = v;
#pragma unroll
    for (int o = 1; o < 32; o <<= 1) {
        uint32_t t = __shfl_up_sync(FULLMASK, inc, o);
        if (lane >= o) inc += t;
    }
    if (lane == 31 && w < 8) s_wsum[w] = inc;
    __syncthreads();
    if (w == 0 && lane < 8) {
        uint32_t x0 = s_wsum[lane];
        uint32_t i2 = x0;
#pragma unroll
        for (int o = 1; o < 8; o <<= 1) {
            uint32_t t = __shfl_up_sync(0xffu, i2, o);
            if (lane >= o) i2 += t;
        }
        s_wsum[lane] = i2 - x0;   // exclusive warp offset
    }
    __syncthreads();
    return inc - v + ((tid < 256) ? s_wsum[w] : 0u);
}

// ---------------------------------------------------------------------------
// One CTA / segment. Per 8192-elem chunk:
//   rank: 16 warp-strided items, match_any + per-warp running digit counters
//   scan: per-digit warp totals (uint16) -> warp-exclusive + digit-exclusive
//   exchange: scatter to smem by local rank, then coalesced global write
// Last pass (FUSE): coalesced read of init_sorted[target] + |diff| reduce.
template <bool FUSE>
__global__ __launch_bounds__(NT, 2) void k_pass(int pass,
                                                const float* __restrict__ init_sorted) {
    __shared__ uint16_t s_cnt[256][NWARP];   // [digit][warp] counts / warp-excl
    __shared__ uint32_t s_exch[CHUNK];
    __shared__ uint32_t s_loc[256];          // local digit start in chunk
    __shared__ uint32_t s_fix[256];          // gbase[d] - s_loc[d]
    __shared__ uint32_t s_wsum[8];
    __shared__ float    s_red[NWARP];

    const uint32_t* __restrict__ in  = (pass & 1) ? g_keyB : g_keyA;
    uint32_t*       __restrict__ out = (pass & 1) ? g_keyA : g_keyB;
    const int shift = 8 * pass;

    const int s   = blockIdx.x;
    const int beg = g_off[s], end = g_off[s + 1];
    const int tid = threadIdx.x, lane = tid & 31, warp = tid >> 5;
    const uint32_t lmask = (1u << lane) - 1u;

    // gbase[d]: running global write base for digit d (register, tid<256 only)
    uint32_t h = (tid < 256) ? g_hist[s][pass][tid] : 0u;
    uint32_t gbase = (uint32_t)beg + scan256(h, tid, s_wsum);

    const int nchunk = (end - beg + CHUNK - 1) / CHUNK;
    float acc = 0.f;

    for (int c = 0; c < nchunk; c++) {
        const int cbeg = beg + c * CHUNK;
        const int vc   = min(CHUNK, end - cbeg);

        // zero rank table (prev chunk's last reads fenced by loop-end barrier)
        for (int i = tid; i < 256 * NWARP / 2; i += NT)
            ((uint32_t*)s_cnt)[i] = 0;
        __syncthreads();

        // ---- rank 16 items (warp-strided: order (j,lane) == memory order)
        uint32_t keys[IT];
        uint16_t rnk[IT];
        const int ibase = cbeg + warp * (IT * 32) + lane;
#pragma unroll
        for (int j = 0; j < IT; j++) {
            int idx = ibase + j * 32;
            bool valid = idx < end;
            uint32_t k = valid ? in[idx] : 0u;
            keys[j] = k;
            uint32_t d = (k >> shift) & 255u;
            uint32_t vm = __ballot_sync(FULLMASK, valid);
            uint32_t m  = __match_any_sync(FULLMASK, d) & vm;
            uint32_t cur = 0;
            if (valid && ((m & lmask) == 0)) {
                cur = s_cnt[d][warp];
                s_cnt[d][warp] = (uint16_t)(cur + (uint32_t)__popc(m));
            }
            int ldr = m ? (__ffs(m) - 1) : 0;
            cur = __shfl_sync(FULLMASK, cur, ldr);
            rnk[j] = (uint16_t)(cur + (uint32_t)__popc(m & lmask));
            __syncwarp();
        }
        __syncthreads();

        // ---- per-digit warp totals -> warp-exclusive in place
        uint32_t tot = 0;
        if (tid < 256) {
            uint32_t run = 0;
#pragma unroll
            for (int w = 0; w < NWARP; w++) {
                uint32_t t = s_cnt[tid][w];
                s_cnt[tid][w] = (uint16_t)run;
                run += t;
            }
            tot = run;
        }
        uint32_t excl = scan256(tot, tid, s_wsum);   // digit start in chunk
        if (tid < 256) {
            s_loc[tid] = excl;
            s_fix[tid] = gbase - excl;
            gbase += tot;
        }
        __syncthreads();

        // ---- scatter to smem exchange by local rank
#pragma unroll
        for (int j = 0; j < IT; j++) {
            int idx = ibase + j * 32;
            if (idx < end) {
                uint32_t d = (keys[j] >> shift) & 255u;
                uint32_t p = s_loc[d] + (uint32_t)s_cnt[d][warp] + (uint32_t)rnk[j];
                s_exch[p] = keys[j];
            }
        }
        __syncthreads();

        // ---- coalesced global scatter (same-digit runs -> contiguous addrs)
#pragma unroll
        for (int j = 0; j < IT; j++) {
            int p = j * NT + tid;
            if (p < vc) {
                uint32_t k = s_exch[p];
                uint32_t d = (k >> shift) & 255u;
                uint32_t g = s_fix[d] + (uint32_t)p;
                if (FUSE) acc += fabsf(unflip(k) - init_sorted[g]);
                else      out[g] = k;
            }
        }
        __syncthreads();
    }

    if (FUSE) {
#pragma unroll
        for (int o = 16; o; o >>= 1) acc += __shfl_down_sync(FULLMASK, acc, o);
        if (lane == 0) s_red[warp] = acc;
        __syncthreads();
        if (warp == 0) {
            float v = (lane < NWARP) ? s_red[lane] : 0.f;
#pragma unroll
            for (int o = 8; o; o >>= 1) v += __shfl_down_sync(FULLMASK, v, o);
            if (lane == 0) {
                int L = end - beg;
                g_emd[s] = (L > 0) ? v / (float)L : 0.f;
            }
        }
    }
}

// ---------------------------------------------------------------------------
__global__ void k_final(float* __restrict__ outp) {
    __shared__ float sh[256];
    int tid = threadIdx.x;
    sh[tid] = (tid < NSEG) ? g_emd[tid] : 0.f;
    __syncthreads();
    for (int o = 128; o; o >>= 1) {
        if (tid < o) sh[tid] += sh[tid + o];
        __syncthreads();
    }
    if (tid == 0) outp[0] = sh[0] * (1e-3f / (float)NSEG);
}

// ---------------------------------------------------------------------------
extern "C" void kernel_launch(void* const* d_in, const int* in_sizes, int n_in,
                              void* d_out, int out_size) {
    const float* x    = (const float*)d_in[0];
    const float* init = (const float*)d_in[1];
    const int*   seg  = (const int*)d_in[2];
    int n = in_sizes[0];

    k_offsets<<<1, 256>>>(seg, n);
    k_hist<<<NSEG, NT>>>(x);
    k_pass<false><<<NSEG, NT>>>(0, nullptr);
    k_pass<false><<<NSEG, NT>>>(1, nullptr);
    k_pass<false><<<NSEG, NT>>>(2, nullptr);
    k_pass<true ><<<NSEG, NT>>>(3, init);
    k_final<<<1, 256>>>((float*)d_out);
}

// round 4
// speedup vs baseline: 1.4207x; 1.3300x over previous
#include <cuda_runtime.h>
#include <stdint.h>

// EarthMoversDistanceRegularizer v4: tile-parallel segmented LSD radix sort
// (4096-elem tiles, ~2250 CTAs, AGG-only decoupled lookback per segment) +
// fused |x_sorted - initial_sorted| reduction on the last pass.

#define NSEG     200
#define NMAX     8388608
#define NT       512
#define NWARP    16
#define IT       8
#define TILE     (NT * IT)              // 4096
#define MAXT     2304                   // >= NMAX/TILE + NSEG = 2248
#define FULLMASK 0xffffffffu
#define FLAGBIT  (1u << 30)
#define CNTMASK  0x3fffffffu

__device__ uint32_t g_keyA[NMAX];
__device__ uint32_t g_keyB[NMAX];
__device__ int      g_off[NSEG + 1];
__device__ int      g_toff[NSEG + 1];
__device__ int      g_tseg[MAXT];
__device__ uint32_t g_hist[NSEG][4][256];
__device__ uint32_t g_status[4][MAXT][256];
__device__ float    g_part[MAXT];

__device__ __forceinline__ uint32_t flipf(uint32_t u) {
    return (u & 0x80000000u) ? ~u : (u | 0x80000000u);
}
__device__ __forceinline__ float unflip(uint32_t k) {
    uint32_t u = (k & 0x80000000u) ? (k & 0x7fffffffu) : ~k;
    return __uint_as_float(u);
}
__device__ __forceinline__ void st_rel(uint32_t* p, uint32_t v) {
    asm volatile("st.release.gpu.u32 [%0], %1;" :: "l"(p), "r"(v) : "memory");
}
__device__ __forceinline__ uint32_t ld_acq(const uint32_t* p) {
    uint32_t v;
    asm volatile("ld.acquire.gpu.u32 %0, [%1];" : "=r"(v) : "l"(p) : "memory");
    return v;
}

// ---------------------------------------------------------------------------
__global__ void k_offsets(const int* __restrict__ seg, int n) {
    int s = threadIdx.x;
    if (s > NSEG) return;
    int lo = 0, hi = n;
    while (lo < hi) {
        int mid = (lo + hi) >> 1;
        if (seg[mid] < s) lo = mid + 1; else hi = mid;
    }
    g_off[s] = lo;
}

// ---------------------------------------------------------------------------
// Exclusive prefix over values held by threads 0..255 (others pass 0).
// All threads of the block must call (contains barriers).
__device__ __forceinline__ uint32_t scan256(uint32_t v, int tid, uint32_t* s_wsum) {
    int lane = tid & 31, w = tid >> 5;
    uint32_t inc = v;
#pragma unroll
    for (int o = 1; o < 32; o <<= 1) {
        uint32_t t = __shfl_up_sync(FULLMASK, inc, o);
        if (lane >= o) inc += t;
    }
    if (lane == 31 && w < 8) s_wsum[w] = inc;
    __syncthreads();
    if (w == 0 && lane < 8) {
        uint32_t x0 = s_wsum[lane];
        uint32_t i2 = x0;
#pragma unroll
        for (int o = 1; o < 8; o <<= 1) {
            uint32_t t = __shfl_up_sync(0xffu, i2, o);
            if (lane >= o) i2 += t;
        }
        s_wsum[lane] = i2 - x0;
    }
    __syncthreads();
    return inc - v + ((tid < 256) ? s_wsum[w] : 0u);
}

// ---------------------------------------------------------------------------
// Tile offsets per segment + tile->segment map. One CTA, 256 threads.
__global__ void k_toff() {
    __shared__ uint32_t s_wsum[8];
    int tid = threadIdx.x;
    uint32_t nt = 0;
    if (tid < NSEG) {
        int len = g_off[tid + 1] - g_off[tid];
        nt = (uint32_t)((len + TILE - 1) / TILE);
    }
    uint32_t excl = scan256(nt, tid, s_wsum);
    if (tid <= NSEG) g_toff[tid] = (int)excl;
    for (int t = tid; t < MAXT; t += 256) g_tseg[t] = -1;
    __syncthreads();
    if (tid < NSEG)
        for (uint32_t t = 0; t < nt; t++) g_tseg[excl + t] = tid;
}

// ---------------------------------------------------------------------------
__global__ void k_zero() {
    uint32_t* p = &g_status[0][0][0];
    const int total = 4 * MAXT * 256;
    for (int i = blockIdx.x * blockDim.x + threadIdx.x; i < total;
         i += gridDim.x * blockDim.x)
        p[i] = 0;
    uint32_t* h = &g_hist[0][0][0];
    for (int i = blockIdx.x * blockDim.x + threadIdx.x; i < NSEG * 4 * 256;
         i += gridDim.x * blockDim.x)
        h[i] = 0;
}

// ---------------------------------------------------------------------------
// Tile-parallel: convert float->sortable uint into g_keyA and accumulate the
// 4 digit-position histograms per segment. 4-way replicated smem counters to
// break the skewed high-byte atomic serialization.
__global__ __launch_bounds__(NT) void k_hist(const float* __restrict__ x) {
    __shared__ uint32_t h4[4][4][256];
    const int b = blockIdx.x;
    const int s = g_tseg[b];
    if (s < 0) return;
    const int tid = threadIdx.x, lane = tid & 31, warp = tid >> 5;
    const uint32_t lmask = (1u << lane) - 1u;
    const int rep = warp & 3;

    const int t    = b - g_toff[s];
    const int tbeg = g_off[s] + t * TILE;
    const int tend = min(tbeg + TILE, g_off[s + 1]);

    for (int i = tid; i < 4 * 4 * 256; i += NT) ((uint32_t*)h4)[i] = 0;
    __syncthreads();

    for (int i = tbeg + tid; i < tend; i += NT) {
        uint32_t k = flipf(__float_as_uint(x[i]));
        g_keyA[i] = k;
#pragma unroll
        for (int p = 0; p < 4; p++) {
            uint32_t d = (k >> (8 * p)) & 255u;
            uint32_t m = __match_any_sync(__activemask(), d);
            if ((m & lmask) == 0)
                atomicAdd(&h4[p][rep][d], (uint32_t)__popc(m));
        }
    }
    __syncthreads();
    for (int i = tid; i < 4 * 256; i += NT) {
        int p = i >> 8, d = i & 255;
        uint32_t v = h4[p][0][d] + h4[p][1][d] + h4[p][2][d] + h4[p][3][d];
        if (v) atomicAdd(&g_hist[s][p][d], v);
    }
}

// ---------------------------------------------------------------------------
// One CTA per 4096-elem tile. Stable rank in tile, AGG-only lookback over
// same-segment predecessor tiles for the cross-tile digit prefix, smem
// exchange, coalesced global scatter. FUSE: |diff| partial sum -> g_part.
template <bool FUSE>
__global__ __launch_bounds__(NT, 3) void k_scatter(int pass,
                                                   const float* __restrict__ init_sorted) {
    __shared__ uint16_t s_cnt[256][NWARP];
    __shared__ uint32_t s_exch[TILE];
    __shared__ uint32_t s_loc[256];
    __shared__ uint32_t s_fix[256];
    __shared__ uint32_t s_wsum[8];
    __shared__ float    s_red[NWARP];

    const int b = blockIdx.x;
    const int s = g_tseg[b];
    if (s < 0) return;

    const uint32_t* __restrict__ in  = (pass & 1) ? g_keyB : g_keyA;
    uint32_t*       __restrict__ out = (pass & 1) ? g_keyA : g_keyB;
    const int shift = 8 * pass;

    const int tid = threadIdx.x, lane = tid & 31, warp = tid >> 5;
    const uint32_t lmask = (1u << lane) - 1u;

    const int beg  = g_off[s], end = g_off[s + 1];
    const int t    = b - g_toff[s];
    const int tbeg = beg + t * TILE;
    const int tend = min(tbeg + TILE, end);
    const int vc   = tend - tbeg;

    for (int i = tid; i < 256 * NWARP / 2; i += NT) ((uint32_t*)s_cnt)[i] = 0;
    __syncthreads();

    // ---- load 8 warp-strided items (batched for MLP), then rank serially
    uint32_t keys[IT];
    const int ibase = tbeg + warp * (IT * 32) + lane;
#pragma unroll
    for (int j = 0; j < IT; j++) {
        int idx = ibase + j * 32;
        keys[j] = (idx < tend) ? in[idx] : 0u;
    }
    uint16_t rnk[IT];
#pragma unroll
    for (int j = 0; j < IT; j++) {
        int idx = ibase + j * 32;
        bool valid = idx < tend;
        uint32_t d = (keys[j] >> shift) & 255u;
        uint32_t vm = __ballot_sync(FULLMASK, valid);
        uint32_t m  = __match_any_sync(FULLMASK, d) & vm;
        uint32_t cur = 0;
        if (valid && ((m & lmask) == 0)) {
            cur = s_cnt[d][warp];
            s_cnt[d][warp] = (uint16_t)(cur + (uint32_t)__popc(m));
        }
        int ldr = m ? (__ffs(m) - 1) : 0;
        cur = __shfl_sync(FULLMASK, cur, ldr);
        rnk[j] = (uint16_t)(cur + (uint32_t)__popc(m & lmask));
        __syncwarp();
    }
    __syncthreads();

    // ---- per-digit warp totals -> warp-exclusive in place; publish count
    uint32_t tot = 0;
    if (tid < 256) {
        uint32_t run = 0;
#pragma unroll
        for (int w = 0; w < NWARP; w++) {
            uint32_t c = s_cnt[tid][w];
            s_cnt[tid][w] = (uint16_t)run;
            run += c;
        }
        tot = run;
        st_rel(&g_status[pass][b][tid], tot | FLAGBIT);   // unblock successors
    }

    // tile-local digit starts + segment digit bases
    uint32_t loc = scan256(tot, tid, s_wsum);
    uint32_t h   = (tid < 256) ? g_hist[s][pass][tid] : 0u;
    uint32_t segx = scan256(h, tid, s_wsum);

    // ---- AGG-only lookback: sum digit counts of predecessor tiles
    if (tid < 256) {
        uint32_t excl = 0;
        for (int pt = b - 1; pt >= b - t; pt--) {
            uint32_t v;
            do { v = ld_acq(&g_status[pass][pt][tid]); } while (v == 0);
            excl += v & CNTMASK;
        }
        s_loc[tid] = loc;
        s_fix[tid] = (uint32_t)beg + segx + excl - loc;
    }
    __syncthreads();

    // ---- scatter to smem exchange by tile-local rank
#pragma unroll
    for (int j = 0; j < IT; j++) {
        int idx = ibase + j * 32;
        if (idx < tend) {
            uint32_t d = (keys[j] >> shift) & 255u;
            uint32_t p = s_loc[d] + (uint32_t)s_cnt[d][warp] + (uint32_t)rnk[j];
            s_exch[p] = keys[j];
        }
    }
    __syncthreads();

    // ---- coalesced global pass (same-digit runs -> contiguous addresses)
    float acc = 0.f;
#pragma unroll
    for (int j = 0; j < IT; j++) {
        int p = j * NT + tid;
        if (p < vc) {
            uint32_t k = s_exch[p];
            uint32_t d = (k >> shift) & 255u;
            uint32_t g = s_fix[d] + (uint32_t)p;
            if (FUSE) acc += fabsf(unflip(k) - init_sorted[g]);
            else      out[g] = k;
        }
    }

    if (FUSE) {
#pragma unroll
        for (int o = 16; o; o >>= 1) acc += __shfl_down_sync(FULLMASK, acc, o);
        if (lane == 0) s_red[warp] = acc;
        __syncthreads();
        if (warp == 0) {
            float v = (lane < NWARP) ? s_red[lane] : 0.f;
#pragma unroll
            for (int o = 8; o; o >>= 1) v += __shfl_down_sync(FULLMASK, v, o);
            if (lane == 0) g_part[b] = v;
        }
    }
}

// ---------------------------------------------------------------------------
// Deterministic per-segment gather of tile partials, mean over segments.
__global__ void k_final(float* __restrict__ outp) {
    __shared__ float sh[256];
    int tid = threadIdx.x;
    float v = 0.f;
    if (tid < NSEG) {
        int len = g_off[tid + 1] - g_off[tid];
        float sum = 0.f;
        for (int t = g_toff[tid]; t < g_toff[tid + 1]; t++) sum += g_part[t];
        v = (len > 0) ? sum / (float)len : 0.f;
    }
    sh[tid] = v;
    __syncthreads();
    for (int o = 128; o; o >>= 1) {
        if (tid < o) sh[tid] += sh[tid + o];
        __syncthreads();
    }
    if (tid == 0) outp[0] = sh[0] * (1e-3f / (float)NSEG);
}

// ---------------------------------------------------------------------------
extern "C" void kernel_launch(void* const* d_in, const int* in_sizes, int n_in,
                              void* d_out, int out_size) {
    const float* x    = (const float*)d_in[0];
    const float* init = (const float*)d_in[1];
    const int*   seg  = (const int*)d_in[2];
    int n = in_sizes[0];

    k_offsets<<<1, 256>>>(seg, n);
    k_toff<<<1, 256>>>();
    k_zero<<<512, 512>>>();
    k_hist<<<MAXT, NT>>>(x);
    k_scatter<false><<<MAXT, NT>>>(0, nullptr);
    k_scatter<false><<<MAXT, NT>>>(1, nullptr);
    k_scatter<false><<<MAXT, NT>>>(2, nullptr);
    k_scatter<true ><<<MAXT, NT>>>(3, init);
    k_final<<<1, 256>>>((float*)d_out);
}

// round 6
// speedup vs baseline: 2.0680x; 1.4557x over previous
#include <cuda_runtime.h>
#include <stdint.h>

// EarthMoversDistanceRegularizer v5: onesweep-style tile-parallel segmented
// LSD radix sort. k_convert builds only the pass-0 histogram; each scatter
// pass accumulates the next pass's histogram inline. 4096-elem tiles,
// AGG-only decoupled lookback, fused |diff| reduction on the last pass.

#define NSEG     200
#define NMAX     8388608
#define NT       512
#define NWARP    16
#define IT       8
#define TILE     (NT * IT)              // 4096
#define MAXT     2304                   // >= NMAX/TILE + NSEG = 2248
#define FULLMASK 0xffffffffu
#define FLAGBIT  (1u << 30)
#define CNTMASK  0x3fffffffu

__device__ uint32_t g_keyA[NMAX];
__device__ uint32_t g_keyB[NMAX];
__device__ int      g_off[NSEG + 1];
__device__ int      g_toff[NSEG + 1];
__device__ int      g_tseg[MAXT];
__device__ uint32_t g_hist[NSEG][4][256];
__device__ uint32_t g_status[4][MAXT][256];
__device__ float    g_part[MAXT];

__device__ __forceinline__ uint32_t flipf(uint32_t u) {
    return (u & 0x80000000u) ? ~u : (u | 0x80000000u);
}
__device__ __forceinline__ float unflip(uint32_t k) {
    uint32_t u = (k & 0x80000000u) ? (k & 0x7fffffffu) : ~k;
    return __uint_as_float(u);
}
__device__ __forceinline__ void st_rel(uint32_t* p, uint32_t v) {
    asm volatile("st.release.gpu.u32 [%0], %1;" :: "l"(p), "r"(v) : "memory");
}
__device__ __forceinline__ uint32_t ld_acq(const uint32_t* p) {
    uint32_t v;
    asm volatile("ld.acquire.gpu.u32 %0, [%1];" : "=r"(v) : "l"(p) : "memory");
    return v;
}

// ---------------------------------------------------------------------------
__global__ void k_offsets(const int* __restrict__ seg, int n) {
    int s = threadIdx.x;
    if (s > NSEG) return;
    int lo = 0, hi = n;
    while (lo < hi) {
        int mid = (lo + hi) >> 1;
        if (seg[mid] < s) lo = mid + 1; else hi = mid;
    }
    g_off[s] = lo;
}

// ---------------------------------------------------------------------------
// Exclusive prefix over values held by threads 0..255 (others pass 0).
// All threads of the block must call (contains barriers).
__device__ __forceinline__ uint32_t scan256(uint32_t v, int tid, uint32_t* s_wsum) {
    int lane = tid & 31, w = tid >> 5;
    uint32_t inc = v;
#pragma unroll
    for (int o = 1; o < 32; o <<= 1) {
        uint32_t t = __shfl_up_sync(FULLMASK, inc, o);
        if (lane >= o) inc += t;
    }
    if (lane == 31 && w < 8) s_wsum[w] = inc;
    __syncthreads();
    if (w == 0 && lane < 8) {
        uint32_t x0 = s_wsum[lane];
        uint32_t i2 = x0;
#pragma unroll
        for (int o = 1; o < 8; o <<= 1) {
            uint32_t t = __shfl_up_sync(0xffu, i2, o);
            if (lane >= o) i2 += t;
        }
        s_wsum[lane] = i2 - x0;
    }
    __syncthreads();
    return inc - v + ((tid < 256) ? s_wsum[w] : 0u);
}

// ---------------------------------------------------------------------------
// Tile offsets per segment + tile->segment map. One CTA, 256 threads.
__global__ void k_toff() {
    __shared__ uint32_t s_wsum[8];
    int tid = threadIdx.x;
    uint32_t nt = 0;
    if (tid < NSEG) {
        int len = g_off[tid + 1] - g_off[tid];
        nt = (uint32_t)((len + TILE - 1) / TILE);
    }
    uint32_t excl = scan256(nt, tid, s_wsum);
    if (tid <= NSEG) g_toff[tid] = (int)excl;
    for (int t = tid; t < MAXT; t += 256) g_tseg[t] = -1;
    __syncthreads();
    if (tid < NSEG)
        for (uint32_t t = 0; t < nt; t++) g_tseg[excl + t] = tid;
}

// ---------------------------------------------------------------------------
__global__ void k_zero() {
    uint32_t* p = &g_status[0][0][0];
    const int total = 4 * MAXT * 256;
    for (int i = blockIdx.x * blockDim.x + threadIdx.x; i < total;
         i += gridDim.x * blockDim.x)
        p[i] = 0;
    uint32_t* h = &g_hist[0][0][0];
    for (int i = blockIdx.x * blockDim.x + threadIdx.x; i < NSEG * 4 * 256;
         i += gridDim.x * blockDim.x)
        h[i] = 0;
}

// ---------------------------------------------------------------------------
// Convert float -> sortable uint and accumulate ONLY the pass-0 (low byte)
// per-segment histogram. Low mantissa byte is ~uniform -> spread smem
// atomics, no match aggregation needed. 4-way replicated to cut conflicts.
__global__ __launch_bounds__(NT) void k_convert(const float* __restrict__ x) {
    __shared__ uint32_t s_h[4][256];
    const int b = blockIdx.x;
    const int s = g_tseg[b];
    if (s < 0) return;
    const int tid = threadIdx.x, rep = (tid >> 5) & 3;

    const int t    = b - g_toff[s];
    const int tbeg = g_off[s] + t * TILE;
    const int tend = min(tbeg + TILE, g_off[s + 1]);

    for (int i = tid; i < 4 * 256; i += NT) ((uint32_t*)s_h)[i] = 0;
    __syncthreads();

    for (int i = tbeg + tid; i < tend; i += NT) {
        uint32_t k = flipf(__float_as_uint(x[i]));
        g_keyA[i] = k;
        atomicAdd(&s_h[rep][k & 255u], 1u);
    }
    __syncthreads();
    if (tid < 256) {
        uint32_t v = s_h[0][tid] + s_h[1][tid] + s_h[2][tid] + s_h[3][tid];
        if (v) atomicAdd(&g_hist[s][0][tid], v);
    }
}

// ---------------------------------------------------------------------------
// One CTA per 4096-elem tile. Stable in-tile rank, AGG-only lookback for the
// cross-tile digit prefix, smem exchange, coalesced global scatter. Each pass
// also accumulates the NEXT pass's digit histogram inline (onesweep).
// FUSE (last pass): |x_sorted - init_sorted| partial sum -> g_part.
template <int PASS, bool FUSE>
__global__ __launch_bounds__(NT, 3) void k_scatter(const float* __restrict__ init_sorted) {
    __shared__ uint16_t s_cnt[256][NWARP];
    __shared__ uint32_t s_exch[TILE];
    __shared__ uint32_t s_loc[256];
    __shared__ uint32_t s_fix[256];
    __shared__ uint32_t s_wsum[8];
    __shared__ uint32_t s_h[4][256];
    __shared__ float    s_red[NWARP];

    const int b = blockIdx.x;
    const int s = g_tseg[b];
    if (s < 0) return;

    const uint32_t* __restrict__ in  = (PASS & 1) ? g_keyB : g_keyA;
    uint32_t*       __restrict__ out = (PASS & 1) ? g_keyA : g_keyB;
    const int shift = 8 * PASS;

    const int tid = threadIdx.x, lane = tid & 31, warp = tid >> 5;
    const uint32_t lmask = (1u << lane) - 1u;

    const int beg  = g_off[s], end = g_off[s + 1];
    const int t    = b - g_toff[s];
    const int tbeg = beg + t * TILE;
    const int tend = min(tbeg + TILE, end);
    const int vc   = tend - tbeg;

    for (int i = tid; i < 256 * NWARP / 2; i += NT) ((uint32_t*)s_cnt)[i] = 0;
    if (PASS < 3)
        for (int i = tid; i < 4 * 256; i += NT) ((uint32_t*)s_h)[i] = 0;
    __syncthreads();

    // ---- load IT warp-strided items (batched for MLP), then rank serially
    uint32_t keys[IT];
    const int ibase = tbeg + warp * (IT * 32) + lane;
#pragma unroll
    for (int j = 0; j < IT; j++) {
        int idx = ibase + j * 32;
        keys[j] = (idx < tend) ? in[idx] : 0u;
    }
    uint16_t rnk[IT];
#pragma unroll
    for (int j = 0; j < IT; j++) {
        int idx = ibase + j * 32;
        bool valid = idx < tend;
        uint32_t d = (keys[j] >> shift) & 255u;
        uint32_t vm = __ballot_sync(FULLMASK, valid);
        uint32_t m  = __match_any_sync(FULLMASK, d) & vm;
        uint32_t cur = 0;
        if (valid && ((m & lmask) == 0)) {
            cur = s_cnt[d][warp];
            s_cnt[d][warp] = (uint16_t)(cur + (uint32_t)__popc(m));
        }
        int ldr = m ? (__ffs(m) - 1) : 0;
        cur = __shfl_sync(FULLMASK, cur, ldr);
        rnk[j] = (uint16_t)(cur + (uint32_t)__popc(m & lmask));
        __syncwarp();
    }
    __syncthreads();

    // ---- per-digit warp totals -> warp-exclusive in place; publish count
    uint32_t tot = 0;
    if (tid < 256) {
        uint32_t run = 0;
#pragma unroll
        for (int w = 0; w < NWARP; w++) {
            uint32_t c = s_cnt[tid][w];
            s_cnt[tid][w] = (uint16_t)run;
            run += c;
        }
        tot = run;
        st_rel(&g_status[PASS][b][tid], tot | FLAGBIT);   // unblock successors
    }

    // ---- single packed scan: high16 = tile-local digit start (tot),
    //      low16 = segment digit base (hist). Cumulative tot <= 4096,
    //      cumulative hist <= segment length < 65536 -> no carry.
    uint32_t h = (tid < 256) ? g_hist[s][PASS][tid] : 0u;
    uint32_t px = scan256((tot << 16) | h, tid, s_wsum);
    uint32_t loc  = px >> 16;
    uint32_t segx = px & 0xffffu;

    // ---- AGG-only lookback, 4-wide MLP batches
    if (tid < 256) {
        uint32_t excl = 0;
        int pt = b - 1;
        const int first = b - t;
        while (pt >= first) {
            int nb = min(4, pt - first + 1);
            uint32_t v0, v1 = 0, v2 = 0, v3 = 0;
            bool ok;
            do {
                v0 = ld_acq(&g_status[PASS][pt][tid]);
                if (nb > 1) v1 = ld_acq(&g_status[PASS][pt - 1][tid]);
                if (nb > 2) v2 = ld_acq(&g_status[PASS][pt - 2][tid]);
                if (nb > 3) v3 = ld_acq(&g_status[PASS][pt - 3][tid]);
                ok = (v0 != 0) && (nb < 2 || v1 != 0) &&
                     (nb < 3 || v2 != 0) && (nb < 4 || v3 != 0);
            } while (!ok);
            excl += (v0 & CNTMASK) + (v1 & CNTMASK) +
                    (v2 & CNTMASK) + (v3 & CNTMASK);
            pt -= nb;
        }
        s_loc[tid] = loc;
        s_fix[tid] = (uint32_t)beg + segx + excl - loc;
    }
    __syncthreads();

    // ---- scatter to smem exchange by tile-local rank
#pragma unroll
    for (int j = 0; j < IT; j++) {
        int idx = ibase + j * 32;
        if (idx < tend) {
            uint32_t d = (keys[j] >> shift) & 255u;
            uint32_t p = s_loc[d] + (uint32_t)s_cnt[d][warp] + (uint32_t)rnk[j];
            s_exch[p] = keys[j];
        }
    }
    __syncthreads();

    // ---- coalesced global pass; inline next-pass histogram (onesweep)
    float acc = 0.f;
#pragma unroll
    for (int j = 0; j < IT; j++) {
        int p = j * NT + tid;
        if (p < vc) {
            uint32_t k = s_exch[p];
            uint32_t d = (k >> shift) & 255u;
            uint32_t g = s_fix[d] + (uint32_t)p;
            if (PASS < 3)
                atomicAdd(&s_h[warp & 3][(k >> (shift + 8)) & 255u], 1u);
            if (FUSE) acc += fabsf(unflip(k) - init_sorted[g]);
            else      out[g] = k;
        }
    }

    if (PASS < 3) {
        __syncthreads();
        if (tid < 256) {
            uint32_t v = s_h[0][tid] + s_h[1][tid] + s_h[2][tid] + s_h[3][tid];
            if (v) atomicAdd(&g_hist[s][PASS + 1][tid], v);
        }
    }

    if (FUSE) {
#pragma unroll
        for (int o = 16; o; o >>= 1) acc += __shfl_down_sync(FULLMASK, acc, o);
        if (lane == 0) s_red[warp] = acc;
        __syncthreads();
        if (warp == 0) {
            float v = (lane < NWARP) ? s_red[lane] : 0.f;
#pragma unroll
            for (int o = 8; o; o >>= 1) v += __shfl_down_sync(FULLMASK, v, o);
            if (lane == 0) g_part[b] = v;
        }
    }
}

// ---------------------------------------------------------------------------
// Deterministic per-segment gather of tile partials, mean over segments.
__global__ void k_final(float* __restrict__ outp) {
    __shared__ float sh[256];
    int tid = threadIdx.x;
    float v = 0.f;
    if (tid < NSEG) {
        int len = g_off[tid + 1] - g_off[tid];
        float sum = 0.f;
        for (int t = g_toff[tid]; t < g_toff[tid + 1]; t++) sum += g_part[t];
        v = (len > 0) ? sum / (float)len : 0.f;
    }
    sh[tid] = v;
    __syncthreads();
    for (int o = 128; o; o >>= 1) {
        if (tid < o) sh[tid] += sh[tid + o];
        __syncthreads();
    }
    if (tid == 0) outp[0] = sh[0] * (1e-3f / (float)NSEG);
}

// ---------------------------------------------------------------------------
extern "C" void kernel_launch(void* const* d_in, const int* in_sizes, int n_in,
                              void* d_out, int out_size) {
    const float* x    = (const float*)d_in[0];
    const float* init = (const float*)d_in[1];
    const int*   seg  = (const int*)d_in[2];
    int n = in_sizes[0];

    k_offsets<<<1, 256>>>(seg, n);
    k_toff<<<1, 256>>>();
    k_zero<<<512, 512>>>();
    k_convert<<<MAXT, NT>>>(x);
    k_scatter<0, false><<<MAXT, NT>>>(nullptr);
    k_scatter<1, false><<<MAXT, NT>>>(nullptr);
    k_scatter<2, false><<<MAXT, NT>>>(nullptr);
    k_scatter<3, true ><<<MAXT, NT>>>(init);
    k_final<<<1, 256>>>((float*)d_out);
}